// round 15
// baseline (speedup 1.0000x reference)
#include <cuda_runtime.h>
#include <mma.h>
#include <stdint.h>
#include <cuda_fp16.h>

using namespace nvcuda;

#define N_NODES 50000
#define N_EDGES 1600000
#define NFEAT   512
#define HIDDEN  128
#define NCLASS  40
#define M_PAD   50048   // 391 * 128
#define SCAN_B  256
#define NBLK    ((N_NODES + SCAN_B - 1) / SCAN_B)   // 196
#define SPLIT   25088   // pipeline split row (multiple of 128)

// ---------------- scratch (static device globals; no allocation) ----------------
__device__ __half g_support1h[(size_t)M_PAD * HIDDEN];   // x @ W1, fp16
__device__ float  g_h[(size_t)N_NODES * HIDDEN];         // dropout(relu(spmm+b1)), fp32
__device__ float  g_support2[(size_t)N_NODES * NCLASS];  // h @ W2, fp32
__device__ int    g_counts[N_NODES];                     // zero at load; re-zeroed in local_scan
__device__ int    g_row_ptr[N_NODES + 1];
__device__ int    g_cursor[N_NODES];
__device__ int    g_block_sums[NBLK];
__device__ int2   g_edges[N_EDGES];                      // (col, val-bits) sorted by row

// ---------------- CSR build ----------------
__global__ void hist_kernel(const int* __restrict__ edge_row) {
    int e = blockIdx.x * blockDim.x + threadIdx.x;
    if (e < N_EDGES) atomicAdd(&g_counts[edge_row[e]], 1);
}

// per-block exclusive scan; zeroes counts for next replay; writes block total
__global__ void local_scan_kernel() {
    __shared__ int sh[SCAN_B];
    int b = blockIdx.x, t = threadIdx.x;
    int idx = b * SCAN_B + t;
    int v = (idx < N_NODES) ? g_counts[idx] : 0;
    if (idx < N_NODES) g_counts[idx] = 0;
    sh[t] = v;
    __syncthreads();
    #pragma unroll
    for (int d = 1; d < SCAN_B; d <<= 1) {
        int x = sh[t];
        int y = (t >= d) ? sh[t - d] : 0;
        __syncthreads();
        sh[t] = x + y;
        __syncthreads();
    }
    if (idx < N_NODES) g_row_ptr[idx] = sh[t] - v;
    if (t == SCAN_B - 1) g_block_sums[b] = sh[t];
}

// add block-prefix offsets; each block redundantly reduces the 196 block sums
__global__ void add_offsets_kernel() {
    __shared__ int sh[256];
    int b = blockIdx.x, t = threadIdx.x;
    sh[t] = (t < NBLK && t < b) ? g_block_sums[t] : 0;
    __syncthreads();
    #pragma unroll
    for (int d = 128; d > 0; d >>= 1) {
        if (t < d) sh[t] += sh[t + d];
        __syncthreads();
    }
    int prefix = sh[0];
    int idx = b * SCAN_B + t;
    if (idx < N_NODES) {
        int r = g_row_ptr[idx] + prefix;
        g_row_ptr[idx] = r;
        g_cursor[idx]  = r;
    }
    if (b == 0 && t == 0) g_row_ptr[N_NODES] = N_EDGES;   // total is static
}

__global__ void scatter_kernel(const int* __restrict__ edge_row,
                               const int* __restrict__ edge_col,
                               const float* __restrict__ edge_vals) {
    int e = blockIdx.x * blockDim.x + threadIdx.x;
    if (e < N_EDGES) {
        int r = edge_row[e];
        int pos = atomicAdd(&g_cursor[r], 1);
        g_edges[pos] = make_int2(edge_col[e], __float_as_int(edge_vals[e]));
    }
}

// ---------------- GEMM1 (fp16 HMMA m16n16k16, double-buffered): support1h = x @ W1
__global__ __launch_bounds__(256) void gemm1_kernel(const float* __restrict__ A,
                                                    const float* __restrict__ B) {
    const int K = NFEAT, N = HIDDEN;
    __shared__ __half As[2][128][24];
    __shared__ __half Bs[2][16][136];
    __shared__ float  stage[8][256];

    int tid = threadIdx.x;
    int warp_id = tid >> 5;
    int lane = tid & 31;
    int wm = warp_id >> 1;
    int wn = warp_id & 1;
    int block_row = blockIdx.x * 128;

    int arow  = tid >> 1;
    int ahalf = (tid & 1) * 8;
    int agrow = block_row + arow;
    bool avalid = agrow < N_NODES;
    const float* abase = A + (size_t)(avalid ? agrow : 0) * K + ahalf;
    int bk = tid >> 4;
    int bn = (tid & 15) * 8;

    wmma::fragment<wmma::accumulator, 16, 16, 16, float> acc[2][4];
    #pragma unroll
    for (int mi = 0; mi < 2; mi++)
        #pragma unroll
        for (int ni = 0; ni < 4; ni++) wmma::fill_fragment(acc[mi][ni], 0.0f);

    auto cvt8 = [](const float4& lo, const float4& hi) {
        __half h[8];
        h[0] = __float2half(lo.x); h[1] = __float2half(lo.y);
        h[2] = __float2half(lo.z); h[3] = __float2half(lo.w);
        h[4] = __float2half(hi.x); h[5] = __float2half(hi.y);
        h[6] = __float2half(hi.z); h[7] = __float2half(hi.w);
        return *(uint4*)h;
    };

    {
        float4 a0 = make_float4(0.f,0.f,0.f,0.f), a1 = a0;
        if (avalid) { a0 = *(const float4*)(abase); a1 = *(const float4*)(abase + 4); }
        *(uint4*)&As[0][arow][ahalf] = cvt8(a0, a1);
        float4 b0 = *(const float4*)&B[(size_t)bk * N + bn];
        float4 b1 = *(const float4*)&B[(size_t)bk * N + bn + 4];
        *(uint4*)&Bs[0][bk][bn] = cvt8(b0, b1);
    }
    __syncthreads();

    int cur = 0;
    for (int kk = 16; kk <= K; kk += 16) {
        bool has_next = kk < K;
        float4 va0, va1, vb0, vb1;
        if (has_next) {
            va0 = make_float4(0.f,0.f,0.f,0.f); va1 = va0;
            if (avalid) {
                const float* src = abase + kk;
                va0 = *(const float4*)(src);
                va1 = *(const float4*)(src + 4);
            }
            vb0 = *(const float4*)&B[(size_t)(kk + bk) * N + bn];
            vb1 = *(const float4*)&B[(size_t)(kk + bk) * N + bn + 4];
        }
        {
            wmma::fragment<wmma::matrix_a, 16, 16, 16, __half, wmma::row_major> af[2];
            wmma::fragment<wmma::matrix_b, 16, 16, 16, __half, wmma::row_major> bf[4];
            #pragma unroll
            for (int mi = 0; mi < 2; mi++)
                wmma::load_matrix_sync(af[mi], &As[cur][wm * 32 + mi * 16][0], 24);
            #pragma unroll
            for (int ni = 0; ni < 4; ni++)
                wmma::load_matrix_sync(bf[ni], &Bs[cur][0][wn * 64 + ni * 16], 136);
            #pragma unroll
            for (int mi = 0; mi < 2; mi++)
                #pragma unroll
                for (int ni = 0; ni < 4; ni++)
                    wmma::mma_sync(acc[mi][ni], af[mi], bf[ni], acc[mi][ni]);
        }
        if (has_next) {
            int nxt = cur ^ 1;
            *(uint4*)&As[nxt][arow][ahalf] = cvt8(va0, va1);
            *(uint4*)&Bs[nxt][bk][bn]      = cvt8(vb0, vb1);
            __syncthreads();
            cur = nxt;
        }
    }

    #pragma unroll
    for (int mi = 0; mi < 2; mi++) {
        #pragma unroll
        for (int ni = 0; ni < 4; ni++) {
            wmma::store_matrix_sync(&stage[warp_id][0], acc[mi][ni], 16, wmma::mem_row_major);
            __syncwarp();
            int r = lane >> 1;
            int c = (lane & 1) * 8;
            const float* src = &stage[warp_id][r * 16 + c];
            __half h[8];
            #pragma unroll
            for (int j = 0; j < 8; j++) h[j] = __float2half(src[j]);
            int grow = block_row + wm * 32 + mi * 16 + r;
            int gcol = wn * 64 + ni * 16 + c;
            *(uint4*)&g_support1h[(size_t)grow * HIDDEN + gcol] = *(uint4*)h;
            __syncwarp();
        }
    }
}

// ---------------- JAX partitionable threefry2x32, key (0, 42) -------------------
__device__ __forceinline__ uint32_t rotl32(uint32_t v, int d) {
    return (v << d) | (v >> (32 - d));
}

__device__ __forceinline__ uint32_t threefry_bits(uint32_t idx) {
    const uint32_t ks0 = 0u, ks1 = 42u;
    const uint32_t ks2 = 0x1BD11BDAu ^ ks0 ^ ks1;
    uint32_t x0 = 0u + ks0;
    uint32_t x1 = idx + ks1;
    #define TFR(r) { x0 += x1; x1 = rotl32(x1, r); x1 ^= x0; }
    TFR(13) TFR(15) TFR(26) TFR(6)
    x0 += ks1; x1 += ks2 + 1u;
    TFR(17) TFR(29) TFR(16) TFR(24)
    x0 += ks2; x1 += ks0 + 2u;
    TFR(13) TFR(15) TFR(26) TFR(6)
    x0 += ks0; x1 += ks1 + 3u;
    TFR(17) TFR(29) TFR(16) TFR(24)
    x0 += ks1; x1 += ks2 + 4u;
    TFR(13) TFR(15) TFR(26) TFR(6)
    x0 += ks2; x1 += ks0 + 5u;
    #undef TFR
    return x0 ^ x1;   // XOR-fold (partitionable 32-bit path)
}

__device__ __forceinline__ float drop_elem(float v, uint32_t idx) {
    return (threefry_bits(idx) >> 31) ? 0.f : v * 2.f;
}

// ---------------- SpMM1: g_h = dropout(relu(A_sp @ support1h + b1)), row-ranged ----
__global__ void spmm1_kernel(const float* __restrict__ b1, int row_off, int row_end) {
    int warp = row_off + ((blockIdx.x * blockDim.x + threadIdx.x) >> 5);
    int lane = threadIdx.x & 31;
    if (warp >= row_end) return;
    int s = g_row_ptr[warp];
    int e = g_row_ptr[warp + 1];

    const uint2* supu = (const uint2*)g_support1h;
    float4 acc = make_float4(0.f, 0.f, 0.f, 0.f);

    int i = s;
    for (; i + 1 < e; i += 2) {
        int2 ev0 = g_edges[i];
        int2 ev1 = g_edges[i + 1];
        uint2 q0 = supu[(size_t)ev0.x * 32 + lane];
        uint2 q1 = supu[(size_t)ev1.x * 32 + lane];
        float v0 = __int_as_float(ev0.y);
        float v1 = __int_as_float(ev1.y);
        float2 f00 = __half22float2(*(__half2*)&q0.x);
        float2 f01 = __half22float2(*(__half2*)&q0.y);
        float2 f10 = __half22float2(*(__half2*)&q1.x);
        float2 f11 = __half22float2(*(__half2*)&q1.y);
        acc.x += v0 * f00.x + v1 * f10.x;
        acc.y += v0 * f00.y + v1 * f10.y;
        acc.z += v0 * f01.x + v1 * f11.x;
        acc.w += v0 * f01.y + v1 * f11.y;
    }
    if (i < e) {
        int2 ev = g_edges[i];
        uint2 q = supu[(size_t)ev.x * 32 + lane];
        float v = __int_as_float(ev.y);
        float2 f0 = __half22float2(*(__half2*)&q.x);
        float2 f1 = __half22float2(*(__half2*)&q.y);
        acc.x += v * f0.x;
        acc.y += v * f0.y;
        acc.z += v * f1.x;
        acc.w += v * f1.y;
    }

    float4 bb = ((const float4*)b1)[lane];
    acc.x = fmaxf(acc.x + bb.x, 0.f);
    acc.y = fmaxf(acc.y + bb.y, 0.f);
    acc.z = fmaxf(acc.z + bb.z, 0.f);
    acc.w = fmaxf(acc.w + bb.w, 0.f);
    uint32_t base = (uint32_t)warp * 128u + (uint32_t)lane * 4u;
    acc.x = drop_elem(acc.x, base + 0u);
    acc.y = drop_elem(acc.y, base + 1u);
    acc.z = drop_elem(acc.z, base + 2u);
    acc.w = drop_elem(acc.w, base + 3u);
    ((float4*)g_h)[(size_t)warp * 32 + lane] = acc;
}

// ---------------- GEMM2 (scalar): support2 = g_h @ W2[128,40], row-ranged ----------------
__global__ __launch_bounds__(128) void gemm2_kernel(const float* __restrict__ B, int row_off) {
    const int M = N_NODES, K = HIDDEN, N = NCLASS;
    __shared__ float As[16][132];
    __shared__ float Bs[16][40];
    int tid = threadIdx.x;
    int tx = tid & 7;
    int ty = tid >> 3;
    int block_row = row_off + blockIdx.x * 128;

    float acc[8][5];
    #pragma unroll
    for (int i = 0; i < 8; i++)
        #pragma unroll
        for (int j = 0; j < 5; j++) acc[i][j] = 0.f;

    for (int kk = 0; kk < K; kk += 16) {
        #pragma unroll
        for (int i = 0; i < 4; i++) {
            int li = tid * 4 + i;
            int ar = li >> 2;
            int ak = (li & 3) * 4;
            float4 av = make_float4(0.f, 0.f, 0.f, 0.f);
            int grow = block_row + ar;
            if (grow < M) av = *(const float4*)&g_h[(size_t)grow * K + kk + ak];
            As[ak + 0][ar] = av.x;
            As[ak + 1][ar] = av.y;
            As[ak + 2][ar] = av.z;
            As[ak + 3][ar] = av.w;
        }
        #pragma unroll
        for (int j = 0; j < 5; j++) {
            int idx = tid + j * 128;
            int bk = idx / 40;
            int bn = idx % 40;
            Bs[bk][bn] = B[(size_t)(kk + bk) * N + bn];
        }
        __syncthreads();
        #pragma unroll
        for (int k = 0; k < 16; k++) {
            float ra[8], rb[5];
            #pragma unroll
            for (int i = 0; i < 8; i++) ra[i] = As[k][ty * 8 + i];
            #pragma unroll
            for (int j = 0; j < 5; j++) rb[j] = Bs[k][tx * 5 + j];
            #pragma unroll
            for (int i = 0; i < 8; i++)
                #pragma unroll
                for (int j = 0; j < 5; j++)
                    acc[i][j] += ra[i] * rb[j];
        }
        __syncthreads();
    }
    #pragma unroll
    for (int i = 0; i < 8; i++) {
        int grow = block_row + ty * 8 + i;
        if (grow < M) {
            #pragma unroll
            for (int j = 0; j < 5; j++)
                g_support2[(size_t)grow * N + tx * 5 + j] = acc[i][j];
        }
    }
}

// ---------------- SpMM2: out = relu(A_sp @ support2 + b2) ----------------
__global__ void spmm2_kernel(const float* __restrict__ b2, float* __restrict__ out) {
    int warp = (blockIdx.x * blockDim.x + threadIdx.x) >> 5;
    int lane = threadIdx.x & 31;
    if (warp >= N_NODES) return;
    int s = g_row_ptr[warp];
    int e = g_row_ptr[warp + 1];
    bool second = lane < (NCLASS - 32);
    float a0 = 0.f, a1 = 0.f;
    int i = s;
    for (; i + 1 < e; i += 2) {
        int2 ev0 = g_edges[i];
        int2 ev1 = g_edges[i + 1];
        const float* p0 = g_support2 + (size_t)ev0.x * NCLASS;
        const float* p1 = g_support2 + (size_t)ev1.x * NCLASS;
        float v0 = __int_as_float(ev0.y);
        float v1 = __int_as_float(ev1.y);
        a0 += v0 * p0[lane] + v1 * p1[lane];
        if (second) a1 += v0 * p0[32 + lane] + v1 * p1[32 + lane];
    }
    if (i < e) {
        int2 ev = g_edges[i];
        float v = __int_as_float(ev.y);
        const float* p = g_support2 + (size_t)ev.x * NCLASS;
        a0 += v * p[lane];
        if (second) a1 += v * p[32 + lane];
    }
    out[(size_t)warp * NCLASS + lane] = fmaxf(a0 + b2[lane], 0.f);
    if (second)
        out[(size_t)warp * NCLASS + 32 + lane] = fmaxf(a1 + b2[32 + lane], 0.f);
}

// ---------------- launch ----------------
extern "C" void kernel_launch(void* const* d_in, const int* in_sizes, int n_in,
                              void* d_out, int out_size) {
    const float* x         = (const float*)d_in[0];
    const int*   edge_row  = (const int*)d_in[1];
    const int*   edge_col  = (const int*)d_in[2];
    const float* edge_vals = (const float*)d_in[3];
    const float* W1        = (const float*)d_in[4];
    const float* b1        = (const float*)d_in[5];
    const float* W2        = (const float*)d_in[6];
    const float* b2        = (const float*)d_in[7];
    float* out = (float*)d_out;

    static cudaStream_t s2 = nullptr;
    static cudaEvent_t evFork = nullptr, evJoin = nullptr;
    static cudaEvent_t ev1 = nullptr, ev2 = nullptr, evJ2 = nullptr;
    if (!s2) {
        cudaStreamCreateWithFlags(&s2, cudaStreamNonBlocking);
        cudaEventCreateWithFlags(&evFork, cudaEventDisableTiming);
        cudaEventCreateWithFlags(&evJoin, cudaEventDisableTiming);
        cudaEventCreateWithFlags(&ev1, cudaEventDisableTiming);
        cudaEventCreateWithFlags(&ev2, cudaEventDisableTiming);
        cudaEventCreateWithFlags(&evJ2, cudaEventDisableTiming);
    }

    // fork: GEMM1 (depends only on x, W1) concurrent with CSR build
    cudaEventRecord(evFork, 0);
    cudaStreamWaitEvent(s2, evFork, 0);
    gemm1_kernel<<<M_PAD / 128, 256, 0, s2>>>(x, W1);
    cudaEventRecord(evJoin, s2);

    // CSR build on main stream
    hist_kernel<<<(N_EDGES + 255) / 256, 256>>>(edge_row);
    local_scan_kernel<<<NBLK, SCAN_B>>>();
    add_offsets_kernel<<<NBLK, 256>>>();
    scatter_kernel<<<(N_EDGES + 255) / 256, 256>>>(edge_row, edge_col, edge_vals);

    // join: spmm1 needs both CSR and support1; pipeline spmm1/gemm2 in halves
    cudaStreamWaitEvent(0, evJoin, 0);
    spmm1_kernel<<<(SPLIT * 32) / 128, 128>>>(b1, 0, SPLIT);
    cudaEventRecord(ev1, 0);
    spmm1_kernel<<<((N_NODES - SPLIT) * 32 + 127) / 128, 128>>>(b1, SPLIT, N_NODES);
    cudaEventRecord(ev2, 0);

    // gemm2 halves on s2, each starting as soon as its h rows are ready
    cudaStreamWaitEvent(s2, ev1, 0);
    gemm2_kernel<<<SPLIT / 128, 128, 0, s2>>>(W2, 0);
    cudaStreamWaitEvent(s2, ev2, 0);
    gemm2_kernel<<<(N_NODES - SPLIT + 127) / 128, 128, 0, s2>>>(W2, SPLIT);
    cudaEventRecord(evJ2, s2);

    // spmm2 needs all of support2
    cudaStreamWaitEvent(0, evJ2, 0);
    spmm2_kernel<<<(N_NODES * 32 + 127) / 128, 128>>>(b2, out);
}

// round 16
// speedup vs baseline: 1.1787x; 1.1787x over previous
#include <cuda_runtime.h>
#include <mma.h>
#include <stdint.h>
#include <cuda_fp16.h>

using namespace nvcuda;

#define N_NODES 50000
#define N_EDGES 1600000
#define NFEAT   512
#define HIDDEN  128
#define NCLASS  40
#define M_PAD   50048   // 391 * 128
#define SCAN_B  256
#define NBLK    ((N_NODES + SCAN_B - 1) / SCAN_B)   // 196

// ---------------- scratch (static device globals; no allocation) ----------------
__device__ __half g_support1h[(size_t)M_PAD * HIDDEN];   // x @ W1, fp16
__device__ float  g_h[(size_t)N_NODES * HIDDEN];         // dropout(relu(spmm+b1)), fp32
__device__ float  g_support2[(size_t)N_NODES * NCLASS];  // h @ W2, fp32
__device__ int    g_counts[N_NODES];
__device__ int    g_row_ptr[N_NODES + 1];
__device__ int    g_cursor[N_NODES];
__device__ int    g_block_sums[NBLK];
__device__ int2   g_edges[N_EDGES];                      // (col, val-bits) sorted by row

// ---------------- CSR build (R10-exact) ----------------
__global__ void zero_counts_kernel() {
    int i = blockIdx.x * blockDim.x + threadIdx.x;
    if (i < N_NODES) g_counts[i] = 0;
}

__global__ void hist_kernel(const int* __restrict__ edge_row) {
    int e = blockIdx.x * blockDim.x + threadIdx.x;
    if (e < N_EDGES) atomicAdd(&g_counts[edge_row[e]], 1);
}

__global__ void local_scan_kernel() {
    __shared__ int sh[SCAN_B];
    int b = blockIdx.x, t = threadIdx.x;
    int idx = b * SCAN_B + t;
    int v = (idx < N_NODES) ? g_counts[idx] : 0;
    sh[t] = v;
    __syncthreads();
    #pragma unroll
    for (int d = 1; d < SCAN_B; d <<= 1) {
        int x = sh[t];
        int y = (t >= d) ? sh[t - d] : 0;
        __syncthreads();
        sh[t] = x + y;
        __syncthreads();
    }
    if (idx < N_NODES) g_row_ptr[idx] = sh[t] - v;
    if (t == SCAN_B - 1) g_block_sums[b] = sh[t];
}

__global__ void scan_sums_kernel() {
    __shared__ int s2[256];
    int t = threadIdx.x;
    int v = (t < NBLK) ? g_block_sums[t] : 0;
    s2[t] = v;
    __syncthreads();
    #pragma unroll
    for (int d = 1; d < 256; d <<= 1) {
        int x = s2[t];
        int y = (t >= d) ? s2[t - d] : 0;
        __syncthreads();
        s2[t] = x + y;
        __syncthreads();
    }
    if (t < NBLK) g_block_sums[t] = s2[t] - v;
    if (t == 255) g_row_ptr[N_NODES] = s2[255];
}

__global__ void add_offsets_kernel() {
    int b = blockIdx.x, t = threadIdx.x;
    int idx = b * SCAN_B + t;
    if (idx < N_NODES) {
        int r = g_row_ptr[idx] + g_block_sums[b];
        g_row_ptr[idx] = r;
        g_cursor[idx]  = r;
    }
}

__global__ void scatter_kernel(const int* __restrict__ edge_row,
                               const int* __restrict__ edge_col,
                               const float* __restrict__ edge_vals) {
    int e = blockIdx.x * blockDim.x + threadIdx.x;
    if (e < N_EDGES) {
        int r = edge_row[e];
        int pos = atomicAdd(&g_cursor[r], 1);
        g_edges[pos] = make_int2(edge_col[e], __float_as_int(edge_vals[e]));
    }
}

// ---------------- GEMM1 (fp16 HMMA m16n16k16, double-buffered): support1h = x @ W1
__global__ __launch_bounds__(256) void gemm1_kernel(const float* __restrict__ A,
                                                    const float* __restrict__ B) {
    const int K = NFEAT, N = HIDDEN;
    __shared__ __half As[2][128][24];
    __shared__ __half Bs[2][16][136];
    __shared__ float  stage[8][256];

    int tid = threadIdx.x;
    int warp_id = tid >> 5;
    int lane = tid & 31;
    int wm = warp_id >> 1;
    int wn = warp_id & 1;
    int block_row = blockIdx.x * 128;

    int arow  = tid >> 1;
    int ahalf = (tid & 1) * 8;
    int agrow = block_row + arow;
    bool avalid = agrow < N_NODES;
    const float* abase = A + (size_t)(avalid ? agrow : 0) * K + ahalf;
    int bk = tid >> 4;
    int bn = (tid & 15) * 8;

    wmma::fragment<wmma::accumulator, 16, 16, 16, float> acc[2][4];
    #pragma unroll
    for (int mi = 0; mi < 2; mi++)
        #pragma unroll
        for (int ni = 0; ni < 4; ni++) wmma::fill_fragment(acc[mi][ni], 0.0f);

    auto cvt8 = [](const float4& lo, const float4& hi) {
        __half h[8];
        h[0] = __float2half(lo.x); h[1] = __float2half(lo.y);
        h[2] = __float2half(lo.z); h[3] = __float2half(lo.w);
        h[4] = __float2half(hi.x); h[5] = __float2half(hi.y);
        h[6] = __float2half(hi.z); h[7] = __float2half(hi.w);
        return *(uint4*)h;
    };

    {
        float4 a0 = make_float4(0.f,0.f,0.f,0.f), a1 = a0;
        if (avalid) { a0 = *(const float4*)(abase); a1 = *(const float4*)(abase + 4); }
        *(uint4*)&As[0][arow][ahalf] = cvt8(a0, a1);
        float4 b0 = *(const float4*)&B[(size_t)bk * N + bn];
        float4 b1 = *(const float4*)&B[(size_t)bk * N + bn + 4];
        *(uint4*)&Bs[0][bk][bn] = cvt8(b0, b1);
    }
    __syncthreads();

    int cur = 0;
    for (int kk = 16; kk <= K; kk += 16) {
        bool has_next = kk < K;
        float4 va0, va1, vb0, vb1;
        if (has_next) {
            va0 = make_float4(0.f,0.f,0.f,0.f); va1 = va0;
            if (avalid) {
                const float* src = abase + kk;
                va0 = *(const float4*)(src);
                va1 = *(const float4*)(src + 4);
            }
            vb0 = *(const float4*)&B[(size_t)(kk + bk) * N + bn];
            vb1 = *(const float4*)&B[(size_t)(kk + bk) * N + bn + 4];
        }
        {
            wmma::fragment<wmma::matrix_a, 16, 16, 16, __half, wmma::row_major> af[2];
            wmma::fragment<wmma::matrix_b, 16, 16, 16, __half, wmma::row_major> bf[4];
            #pragma unroll
            for (int mi = 0; mi < 2; mi++)
                wmma::load_matrix_sync(af[mi], &As[cur][wm * 32 + mi * 16][0], 24);
            #pragma unroll
            for (int ni = 0; ni < 4; ni++)
                wmma::load_matrix_sync(bf[ni], &Bs[cur][0][wn * 64 + ni * 16], 136);
            #pragma unroll
            for (int mi = 0; mi < 2; mi++)
                #pragma unroll
                for (int ni = 0; ni < 4; ni++)
                    wmma::mma_sync(acc[mi][ni], af[mi], bf[ni], acc[mi][ni]);
        }
        if (has_next) {
            int nxt = cur ^ 1;
            *(uint4*)&As[nxt][arow][ahalf] = cvt8(va0, va1);
            *(uint4*)&Bs[nxt][bk][bn]      = cvt8(vb0, vb1);
            __syncthreads();
            cur = nxt;
        }
    }

    #pragma unroll
    for (int mi = 0; mi < 2; mi++) {
        #pragma unroll
        for (int ni = 0; ni < 4; ni++) {
            wmma::store_matrix_sync(&stage[warp_id][0], acc[mi][ni], 16, wmma::mem_row_major);
            __syncwarp();
            int r = lane >> 1;
            int c = (lane & 1) * 8;
            const float* src = &stage[warp_id][r * 16 + c];
            __half h[8];
            #pragma unroll
            for (int j = 0; j < 8; j++) h[j] = __float2half(src[j]);
            int grow = block_row + wm * 32 + mi * 16 + r;
            int gcol = wn * 64 + ni * 16 + c;
            *(uint4*)&g_support1h[(size_t)grow * HIDDEN + gcol] = *(uint4*)h;
            __syncwarp();
        }
    }
}

// ---------------- JAX partitionable threefry2x32, key (0, 42) -------------------
__device__ __forceinline__ uint32_t rotl32(uint32_t v, int d) {
    return (v << d) | (v >> (32 - d));
}

__device__ __forceinline__ uint32_t threefry_bits(uint32_t idx) {
    const uint32_t ks0 = 0u, ks1 = 42u;
    const uint32_t ks2 = 0x1BD11BDAu ^ ks0 ^ ks1;
    uint32_t x0 = 0u + ks0;
    uint32_t x1 = idx + ks1;
    #define TFR(r) { x0 += x1; x1 = rotl32(x1, r); x1 ^= x0; }
    TFR(13) TFR(15) TFR(26) TFR(6)
    x0 += ks1; x1 += ks2 + 1u;
    TFR(17) TFR(29) TFR(16) TFR(24)
    x0 += ks2; x1 += ks0 + 2u;
    TFR(13) TFR(15) TFR(26) TFR(6)
    x0 += ks0; x1 += ks1 + 3u;
    TFR(17) TFR(29) TFR(16) TFR(24)
    x0 += ks1; x1 += ks2 + 4u;
    TFR(13) TFR(15) TFR(26) TFR(6)
    x0 += ks2; x1 += ks0 + 5u;
    #undef TFR
    return x0 ^ x1;   // XOR-fold (partitionable 32-bit path)
}

__device__ __forceinline__ float drop_elem(float v, uint32_t idx) {
    return (threefry_bits(idx) >> 31) ? 0.f : v * 2.f;
}

// ---------------- SpMM1: g_h = dropout(relu(A_sp @ support1h + b1)), fp16 gather ----
__global__ void spmm1_kernel(const float* __restrict__ b1) {
    int warp = (blockIdx.x * blockDim.x + threadIdx.x) >> 5;
    int lane = threadIdx.x & 31;
    if (warp >= N_NODES) return;
    int s = g_row_ptr[warp];
    int e = g_row_ptr[warp + 1];

    const uint2* supu = (const uint2*)g_support1h;
    float4 acc = make_float4(0.f, 0.f, 0.f, 0.f);

    int i = s;
    for (; i + 1 < e; i += 2) {
        int2 ev0 = g_edges[i];
        int2 ev1 = g_edges[i + 1];
        uint2 q0 = supu[(size_t)ev0.x * 32 + lane];
        uint2 q1 = supu[(size_t)ev1.x * 32 + lane];
        float v0 = __int_as_float(ev0.y);
        float v1 = __int_as_float(ev1.y);
        float2 f00 = __half22float2(*(__half2*)&q0.x);
        float2 f01 = __half22float2(*(__half2*)&q0.y);
        float2 f10 = __half22float2(*(__half2*)&q1.x);
        float2 f11 = __half22float2(*(__half2*)&q1.y);
        acc.x += v0 * f00.x + v1 * f10.x;
        acc.y += v0 * f00.y + v1 * f10.y;
        acc.z += v0 * f01.x + v1 * f11.x;
        acc.w += v0 * f01.y + v1 * f11.y;
    }
    if (i < e) {
        int2 ev = g_edges[i];
        uint2 q = supu[(size_t)ev.x * 32 + lane];
        float v = __int_as_float(ev.y);
        float2 f0 = __half22float2(*(__half2*)&q.x);
        float2 f1 = __half22float2(*(__half2*)&q.y);
        acc.x += v * f0.x;
        acc.y += v * f0.y;
        acc.z += v * f1.x;
        acc.w += v * f1.y;
    }

    float4 bb = ((const float4*)b1)[lane];
    acc.x = fmaxf(acc.x + bb.x, 0.f);
    acc.y = fmaxf(acc.y + bb.y, 0.f);
    acc.z = fmaxf(acc.z + bb.z, 0.f);
    acc.w = fmaxf(acc.w + bb.w, 0.f);
    uint32_t base = (uint32_t)warp * 128u + (uint32_t)lane * 4u;
    acc.x = drop_elem(acc.x, base + 0u);
    acc.y = drop_elem(acc.y, base + 1u);
    acc.z = drop_elem(acc.z, base + 2u);
    acc.w = drop_elem(acc.w, base + 3u);
    ((float4*)g_h)[(size_t)warp * 32 + lane] = acc;
}

// ---------------- GEMM2 (scalar, BM=64 for wave balance): support2 = g_h @ W2 ------
// grid 782 (5.3 waves) instead of 391 (2.6 waves); same k-order -> bit-identical sums.
__global__ __launch_bounds__(128) void gemm2_kernel(const float* __restrict__ B) {
    const int M = N_NODES, K = HIDDEN, N = NCLASS;
    __shared__ float As[16][68];    // [k][m], 64 rows + pad
    __shared__ float Bs[16][40];
    int tid = threadIdx.x;
    int tx = tid & 7;               // cols tx*5
    int ty = tid >> 3;              // rows ty*4 (16 groups of 4)
    int block_row = blockIdx.x * 64;

    float acc[4][5];
    #pragma unroll
    for (int i = 0; i < 4; i++)
        #pragma unroll
        for (int j = 0; j < 5; j++) acc[i][j] = 0.f;

    for (int kk = 0; kk < K; kk += 16) {
        #pragma unroll
        for (int i = 0; i < 2; i++) {
            int li = tid * 2 + i;          // 0..255 float4 slots
            int ar = li >> 2;              // 0..63
            int ak = (li & 3) * 4;
            float4 av = make_float4(0.f, 0.f, 0.f, 0.f);
            int grow = block_row + ar;
            if (grow < M) av = *(const float4*)&g_h[(size_t)grow * K + kk + ak];
            As[ak + 0][ar] = av.x;
            As[ak + 1][ar] = av.y;
            As[ak + 2][ar] = av.z;
            As[ak + 3][ar] = av.w;
        }
        #pragma unroll
        for (int j = 0; j < 5; j++) {
            int idx = tid + j * 128;
            int bk = idx / 40;
            int bn = idx % 40;
            Bs[bk][bn] = B[(size_t)(kk + bk) * N + bn];
        }
        __syncthreads();
        #pragma unroll
        for (int k = 0; k < 16; k++) {
            float ra[4], rb[5];
            #pragma unroll
            for (int i = 0; i < 4; i++) ra[i] = As[k][ty * 4 + i];
            #pragma unroll
            for (int j = 0; j < 5; j++) rb[j] = Bs[k][tx * 5 + j];
            #pragma unroll
            for (int i = 0; i < 4; i++)
                #pragma unroll
                for (int j = 0; j < 5; j++)
                    acc[i][j] += ra[i] * rb[j];
        }
        __syncthreads();
    }
    #pragma unroll
    for (int i = 0; i < 4; i++) {
        int grow = block_row + ty * 4 + i;
        if (grow < M) {
            #pragma unroll
            for (int j = 0; j < 5; j++)
                g_support2[(size_t)grow * N + tx * 5 + j] = acc[i][j];
        }
    }
}

// ---------------- SpMM2: out = relu(A_sp @ support2 + b2) ----------------
__global__ void spmm2_kernel(const float* __restrict__ b2, float* __restrict__ out) {
    int warp = (blockIdx.x * blockDim.x + threadIdx.x) >> 5;
    int lane = threadIdx.x & 31;
    if (warp >= N_NODES) return;
    int s = g_row_ptr[warp];
    int e = g_row_ptr[warp + 1];
    bool second = lane < (NCLASS - 32);
    float a0 = 0.f, a1 = 0.f;
    int i = s;
    for (; i + 1 < e; i += 2) {
        int2 ev0 = g_edges[i];
        int2 ev1 = g_edges[i + 1];
        const float* p0 = g_support2 + (size_t)ev0.x * NCLASS;
        const float* p1 = g_support2 + (size_t)ev1.x * NCLASS;
        float v0 = __int_as_float(ev0.y);
        float v1 = __int_as_float(ev1.y);
        a0 += v0 * p0[lane] + v1 * p1[lane];
        if (second) a1 += v0 * p0[32 + lane] + v1 * p1[32 + lane];
    }
    if (i < e) {
        int2 ev = g_edges[i];
        float v = __int_as_float(ev.y);
        const float* p = g_support2 + (size_t)ev.x * NCLASS;
        a0 += v * p[lane];
        if (second) a1 += v * p[32 + lane];
    }
    out[(size_t)warp * NCLASS + lane] = fmaxf(a0 + b2[lane], 0.f);
    if (second)
        out[(size_t)warp * NCLASS + 32 + lane] = fmaxf(a1 + b2[32 + lane], 0.f);
}

// ---------------- launch ----------------
extern "C" void kernel_launch(void* const* d_in, const int* in_sizes, int n_in,
                              void* d_out, int out_size) {
    const float* x         = (const float*)d_in[0];
    const int*   edge_row  = (const int*)d_in[1];
    const int*   edge_col  = (const int*)d_in[2];
    const float* edge_vals = (const float*)d_in[3];
    const float* W1        = (const float*)d_in[4];
    const float* b1        = (const float*)d_in[5];
    const float* W2        = (const float*)d_in[6];
    const float* b2        = (const float*)d_in[7];
    float* out = (float*)d_out;

    static cudaStream_t s2 = nullptr;
    static cudaEvent_t evFork = nullptr, evJoin = nullptr;
    if (!s2) {
        cudaStreamCreateWithFlags(&s2, cudaStreamNonBlocking);
        cudaEventCreateWithFlags(&evFork, cudaEventDisableTiming);
        cudaEventCreateWithFlags(&evJoin, cudaEventDisableTiming);
    }

    // fork: GEMM1 (depends only on x, W1) concurrent with CSR build
    cudaEventRecord(evFork, 0);
    cudaStreamWaitEvent(s2, evFork, 0);
    gemm1_kernel<<<M_PAD / 128, 256, 0, s2>>>(x, W1);
    cudaEventRecord(evJoin, s2);

    // CSR build on main stream (R10-exact)
    zero_counts_kernel<<<(N_NODES + 255) / 256, 256>>>();
    hist_kernel<<<(N_EDGES + 255) / 256, 256>>>(edge_row);
    local_scan_kernel<<<NBLK, SCAN_B>>>();
    scan_sums_kernel<<<1, 256>>>();
    add_offsets_kernel<<<NBLK, SCAN_B>>>();
    scatter_kernel<<<(N_EDGES + 255) / 256, 256>>>(edge_row, edge_col, edge_vals);

    // join: spmm1 needs both CSR and support1
    cudaStreamWaitEvent(0, evJoin, 0);
    spmm1_kernel<<<(N_NODES * 32 + 127) / 128, 128>>>(b1);

    gemm2_kernel<<<(N_NODES + 63) / 64, 128>>>(W2);
    spmm2_kernel<<<(N_NODES * 32 + 127) / 128, 128>>>(b2, out);
}

// round 17
// speedup vs baseline: 1.2089x; 1.0256x over previous
#include <cuda_runtime.h>
#include <mma.h>
#include <stdint.h>
#include <cuda_fp16.h>

using namespace nvcuda;

#define N_NODES 50000
#define N_EDGES 1600000
#define NFEAT   512
#define HIDDEN  128
#define NCLASS  40
#define M_PAD   50048   // 391*128 = 782*64
#define SCAN_B  256
#define NBLK    ((N_NODES + SCAN_B - 1) / SCAN_B)   // 196

// ---------------- scratch (static device globals; no allocation) ----------------
__device__ __half g_support1h[(size_t)M_PAD * HIDDEN];   // x @ W1, fp16
__device__ float  g_h[(size_t)N_NODES * HIDDEN];         // dropout(relu(spmm+b1)), fp32
__device__ float  g_support2[(size_t)N_NODES * NCLASS];  // h @ W2, fp32
__device__ int    g_counts[N_NODES];
__device__ int    g_row_ptr[N_NODES + 1];
__device__ int    g_cursor[N_NODES];
__device__ int    g_block_sums[NBLK];
__device__ int2   g_edges[N_EDGES];                      // (col, val-bits) sorted by row

// ---------------- CSR build (R10-exact) ----------------
__global__ void zero_counts_kernel() {
    int i = blockIdx.x * blockDim.x + threadIdx.x;
    if (i < N_NODES) g_counts[i] = 0;
}

__global__ void hist_kernel(const int* __restrict__ edge_row) {
    int e = blockIdx.x * blockDim.x + threadIdx.x;
    if (e < N_EDGES) atomicAdd(&g_counts[edge_row[e]], 1);
}

__global__ void local_scan_kernel() {
    __shared__ int sh[SCAN_B];
    int b = blockIdx.x, t = threadIdx.x;
    int idx = b * SCAN_B + t;
    int v = (idx < N_NODES) ? g_counts[idx] : 0;
    sh[t] = v;
    __syncthreads();
    #pragma unroll
    for (int d = 1; d < SCAN_B; d <<= 1) {
        int x = sh[t];
        int y = (t >= d) ? sh[t - d] : 0;
        __syncthreads();
        sh[t] = x + y;
        __syncthreads();
    }
    if (idx < N_NODES) g_row_ptr[idx] = sh[t] - v;
    if (t == SCAN_B - 1) g_block_sums[b] = sh[t];
}

__global__ void scan_sums_kernel() {
    __shared__ int s2[256];
    int t = threadIdx.x;
    int v = (t < NBLK) ? g_block_sums[t] : 0;
    s2[t] = v;
    __syncthreads();
    #pragma unroll
    for (int d = 1; d < 256; d <<= 1) {
        int x = s2[t];
        int y = (t >= d) ? s2[t - d] : 0;
        __syncthreads();
        s2[t] = x + y;
        __syncthreads();
    }
    if (t < NBLK) g_block_sums[t] = s2[t] - v;
    if (t == 255) g_row_ptr[N_NODES] = s2[255];
}

__global__ void add_offsets_kernel() {
    int b = blockIdx.x, t = threadIdx.x;
    int idx = b * SCAN_B + t;
    if (idx < N_NODES) {
        int r = g_row_ptr[idx] + g_block_sums[b];
        g_row_ptr[idx] = r;
        g_cursor[idx]  = r;
    }
}

__global__ void scatter_kernel(const int* __restrict__ edge_row,
                               const int* __restrict__ edge_col,
                               const float* __restrict__ edge_vals) {
    int e = blockIdx.x * blockDim.x + threadIdx.x;
    if (e < N_EDGES) {
        int r = edge_row[e];
        int pos = atomicAdd(&g_cursor[r], 1);
        g_edges[pos] = make_int2(edge_col[e], __float_as_int(edge_vals[e]));
    }
}

// ---------------- GEMM1 (fp16 HMMA m16n16k16, double-buffered, BM=64): support1h = x @ W1
// BM=64, BN=128, BK=16. 8 warps 4x2; warp tile 16x64 (1x4 frags). grid=782 (5.28 waves).
// Same k16-chunk order as BM=128 version -> bit-identical accumulation.
__global__ __launch_bounds__(256) void gemm1_kernel(const float* __restrict__ A,
                                                    const float* __restrict__ B) {
    const int K = NFEAT, N = HIDDEN;
    __shared__ __half As[2][64][24];     // [stage][m][k]
    __shared__ __half Bs[2][16][136];    // [stage][k][n]
    __shared__ float  stage[8][256];

    int tid = threadIdx.x;
    int warp_id = tid >> 5;
    int lane = tid & 31;
    int wm = warp_id >> 1;               // 0..3 -> rows wm*16
    int wn = warp_id & 1;                // 0..1 -> cols wn*64
    int block_row = blockIdx.x * 64;

    // A: each thread loads one float4 (4 floats of one row-quarter)
    int arow  = tid >> 2;                // 0..63
    int ahalf = (tid & 3) * 4;           // 0,4,8,12
    int agrow = block_row + arow;
    bool avalid = agrow < N_NODES;
    const float* abase = A + (size_t)(avalid ? agrow : 0) * K + ahalf;
    // B: each thread loads 8 floats: row bk, cols bn..bn+7
    int bk = tid >> 4;
    int bn = (tid & 15) * 8;

    wmma::fragment<wmma::accumulator, 16, 16, 16, float> acc[4];
    #pragma unroll
    for (int ni = 0; ni < 4; ni++) wmma::fill_fragment(acc[ni], 0.0f);

    auto cvt4 = [](const float4& v) {
        __half h[4];
        h[0] = __float2half(v.x); h[1] = __float2half(v.y);
        h[2] = __float2half(v.z); h[3] = __float2half(v.w);
        return *(uint2*)h;
    };
    auto cvt8 = [](const float4& lo, const float4& hi) {
        __half h[8];
        h[0] = __float2half(lo.x); h[1] = __float2half(lo.y);
        h[2] = __float2half(lo.z); h[3] = __float2half(lo.w);
        h[4] = __float2half(hi.x); h[5] = __float2half(hi.y);
        h[6] = __float2half(hi.z); h[7] = __float2half(hi.w);
        return *(uint4*)h;
    };

    // preload tile 0
    {
        float4 a0 = make_float4(0.f,0.f,0.f,0.f);
        if (avalid) a0 = *(const float4*)(abase);
        *(uint2*)&As[0][arow][ahalf] = cvt4(a0);
        float4 b0 = *(const float4*)&B[(size_t)bk * N + bn];
        float4 b1 = *(const float4*)&B[(size_t)bk * N + bn + 4];
        *(uint4*)&Bs[0][bk][bn] = cvt8(b0, b1);
    }
    __syncthreads();

    int cur = 0;
    for (int kk = 16; kk <= K; kk += 16) {
        bool has_next = kk < K;
        float4 va0, vb0, vb1;
        if (has_next) {
            va0 = make_float4(0.f,0.f,0.f,0.f);
            if (avalid) va0 = *(const float4*)(abase + kk);
            vb0 = *(const float4*)&B[(size_t)(kk + bk) * N + bn];
            vb1 = *(const float4*)&B[(size_t)(kk + bk) * N + bn + 4];
        }
        {
            wmma::fragment<wmma::matrix_a, 16, 16, 16, __half, wmma::row_major> af;
            wmma::fragment<wmma::matrix_b, 16, 16, 16, __half, wmma::row_major> bf[4];
            wmma::load_matrix_sync(af, &As[cur][wm * 16][0], 24);
            #pragma unroll
            for (int ni = 0; ni < 4; ni++)
                wmma::load_matrix_sync(bf[ni], &Bs[cur][0][wn * 64 + ni * 16], 136);
            #pragma unroll
            for (int ni = 0; ni < 4; ni++)
                wmma::mma_sync(acc[ni], af, bf[ni], acc[ni]);
        }
        if (has_next) {
            int nxt = cur ^ 1;
            *(uint2*)&As[nxt][arow][ahalf] = cvt4(va0);
            *(uint4*)&Bs[nxt][bk][bn]      = cvt8(vb0, vb1);
            __syncthreads();
            cur = nxt;
        }
    }

    // epilogue: stage each 16x16 tile, convert to fp16, write uint4
    #pragma unroll
    for (int ni = 0; ni < 4; ni++) {
        wmma::store_matrix_sync(&stage[warp_id][0], acc[ni], 16, wmma::mem_row_major);
        __syncwarp();
        int r = lane >> 1;
        int c = (lane & 1) * 8;
        const float* src = &stage[warp_id][r * 16 + c];
        __half h[8];
        #pragma unroll
        for (int j = 0; j < 8; j++) h[j] = __float2half(src[j]);
        int grow = block_row + wm * 16 + r;     // < M_PAD always
        int gcol = wn * 64 + ni * 16 + c;
        *(uint4*)&g_support1h[(size_t)grow * HIDDEN + gcol] = *(uint4*)h;
        __syncwarp();
    }
}

// ---------------- JAX partitionable threefry2x32, key (0, 42) -------------------
__device__ __forceinline__ uint32_t rotl32(uint32_t v, int d) {
    return (v << d) | (v >> (32 - d));
}

__device__ __forceinline__ uint32_t threefry_bits(uint32_t idx) {
    const uint32_t ks0 = 0u, ks1 = 42u;
    const uint32_t ks2 = 0x1BD11BDAu ^ ks0 ^ ks1;
    uint32_t x0 = 0u + ks0;
    uint32_t x1 = idx + ks1;
    #define TFR(r) { x0 += x1; x1 = rotl32(x1, r); x1 ^= x0; }
    TFR(13) TFR(15) TFR(26) TFR(6)
    x0 += ks1; x1 += ks2 + 1u;
    TFR(17) TFR(29) TFR(16) TFR(24)
    x0 += ks2; x1 += ks0 + 2u;
    TFR(13) TFR(15) TFR(26) TFR(6)
    x0 += ks0; x1 += ks1 + 3u;
    TFR(17) TFR(29) TFR(16) TFR(24)
    x0 += ks1; x1 += ks2 + 4u;
    TFR(13) TFR(15) TFR(26) TFR(6)
    x0 += ks2; x1 += ks0 + 5u;
    #undef TFR
    return x0 ^ x1;   // XOR-fold (partitionable 32-bit path)
}

__device__ __forceinline__ float drop_elem(float v, uint32_t idx) {
    return (threefry_bits(idx) >> 31) ? 0.f : v * 2.f;
}

// ---------------- SpMM1: g_h = dropout(relu(A_sp @ support1h + b1)), fp16 gather ----
__global__ void spmm1_kernel(const float* __restrict__ b1) {
    int warp = (blockIdx.x * blockDim.x + threadIdx.x) >> 5;
    int lane = threadIdx.x & 31;
    if (warp >= N_NODES) return;
    int s = g_row_ptr[warp];
    int e = g_row_ptr[warp + 1];

    const uint2* supu = (const uint2*)g_support1h;
    float4 acc = make_float4(0.f, 0.f, 0.f, 0.f);

    int i = s;
    for (; i + 1 < e; i += 2) {
        int2 ev0 = g_edges[i];
        int2 ev1 = g_edges[i + 1];
        uint2 q0 = supu[(size_t)ev0.x * 32 + lane];
        uint2 q1 = supu[(size_t)ev1.x * 32 + lane];
        float v0 = __int_as_float(ev0.y);
        float v1 = __int_as_float(ev1.y);
        float2 f00 = __half22float2(*(__half2*)&q0.x);
        float2 f01 = __half22float2(*(__half2*)&q0.y);
        float2 f10 = __half22float2(*(__half2*)&q1.x);
        float2 f11 = __half22float2(*(__half2*)&q1.y);
        acc.x += v0 * f00.x + v1 * f10.x;
        acc.y += v0 * f00.y + v1 * f10.y;
        acc.z += v0 * f01.x + v1 * f11.x;
        acc.w += v0 * f01.y + v1 * f11.y;
    }
    if (i < e) {
        int2 ev = g_edges[i];
        uint2 q = supu[(size_t)ev.x * 32 + lane];
        float v = __int_as_float(ev.y);
        float2 f0 = __half22float2(*(__half2*)&q.x);
        float2 f1 = __half22float2(*(__half2*)&q.y);
        acc.x += v * f0.x;
        acc.y += v * f0.y;
        acc.z += v * f1.x;
        acc.w += v * f1.y;
    }

    float4 bb = ((const float4*)b1)[lane];
    acc.x = fmaxf(acc.x + bb.x, 0.f);
    acc.y = fmaxf(acc.y + bb.y, 0.f);
    acc.z = fmaxf(acc.z + bb.z, 0.f);
    acc.w = fmaxf(acc.w + bb.w, 0.f);
    uint32_t base = (uint32_t)warp * 128u + (uint32_t)lane * 4u;
    acc.x = drop_elem(acc.x, base + 0u);
    acc.y = drop_elem(acc.y, base + 1u);
    acc.z = drop_elem(acc.z, base + 2u);
    acc.w = drop_elem(acc.w, base + 3u);
    ((float4*)g_h)[(size_t)warp * 32 + lane] = acc;
}

// ---------------- GEMM2 (scalar, BM=64): support2 = g_h @ W2 ----------------
__global__ __launch_bounds__(128) void gemm2_kernel(const float* __restrict__ B) {
    const int M = N_NODES, K = HIDDEN, N = NCLASS;
    __shared__ float As[16][68];
    __shared__ float Bs[16][40];
    int tid = threadIdx.x;
    int tx = tid & 7;
    int ty = tid >> 3;
    int block_row = blockIdx.x * 64;

    float acc[4][5];
    #pragma unroll
    for (int i = 0; i < 4; i++)
        #pragma unroll
        for (int j = 0; j < 5; j++) acc[i][j] = 0.f;

    for (int kk = 0; kk < K; kk += 16) {
        #pragma unroll
        for (int i = 0; i < 2; i++) {
            int li = tid * 2 + i;
            int ar = li >> 2;
            int ak = (li & 3) * 4;
            float4 av = make_float4(0.f, 0.f, 0.f, 0.f);
            int grow = block_row + ar;
            if (grow < M) av = *(const float4*)&g_h[(size_t)grow * K + kk + ak];
            As[ak + 0][ar] = av.x;
            As[ak + 1][ar] = av.y;
            As[ak + 2][ar] = av.z;
            As[ak + 3][ar] = av.w;
        }
        #pragma unroll
        for (int j = 0; j < 5; j++) {
            int idx = tid + j * 128;
            int bk = idx / 40;
            int bn = idx % 40;
            Bs[bk][bn] = B[(size_t)(kk + bk) * N + bn];
        }
        __syncthreads();
        #pragma unroll
        for (int k = 0; k < 16; k++) {
            float ra[4], rb[5];
            #pragma unroll
            for (int i = 0; i < 4; i++) ra[i] = As[k][ty * 4 + i];
            #pragma unroll
            for (int j = 0; j < 5; j++) rb[j] = Bs[k][tx * 5 + j];
            #pragma unroll
            for (int i = 0; i < 4; i++)
                #pragma unroll
                for (int j = 0; j < 5; j++)
                    acc[i][j] += ra[i] * rb[j];
        }
        __syncthreads();
    }
    #pragma unroll
    for (int i = 0; i < 4; i++) {
        int grow = block_row + ty * 4 + i;
        if (grow < M) {
            #pragma unroll
            for (int j = 0; j < 5; j++)
                g_support2[(size_t)grow * N + tx * 5 + j] = acc[i][j];
        }
    }
}

// ---------------- SpMM2: out = relu(A_sp @ support2 + b2) ----------------
__global__ void spmm2_kernel(const float* __restrict__ b2, float* __restrict__ out) {
    int warp = (blockIdx.x * blockDim.x + threadIdx.x) >> 5;
    int lane = threadIdx.x & 31;
    if (warp >= N_NODES) return;
    int s = g_row_ptr[warp];
    int e = g_row_ptr[warp + 1];
    bool second = lane < (NCLASS - 32);
    float a0 = 0.f, a1 = 0.f;
    int i = s;
    for (; i + 1 < e; i += 2) {
        int2 ev0 = g_edges[i];
        int2 ev1 = g_edges[i + 1];
        const float* p0 = g_support2 + (size_t)ev0.x * NCLASS;
        const float* p1 = g_support2 + (size_t)ev1.x * NCLASS;
        float v0 = __int_as_float(ev0.y);
        float v1 = __int_as_float(ev1.y);
        a0 += v0 * p0[lane] + v1 * p1[lane];
        if (second) a1 += v0 * p0[32 + lane] + v1 * p1[32 + lane];
    }
    if (i < e) {
        int2 ev = g_edges[i];
        float v = __int_as_float(ev.y);
        const float* p = g_support2 + (size_t)ev.x * NCLASS;
        a0 += v * p[lane];
        if (second) a1 += v * p[32 + lane];
    }
    out[(size_t)warp * NCLASS + lane] = fmaxf(a0 + b2[lane], 0.f);
    if (second)
        out[(size_t)warp * NCLASS + 32 + lane] = fmaxf(a1 + b2[32 + lane], 0.f);
}

// ---------------- launch ----------------
extern "C" void kernel_launch(void* const* d_in, const int* in_sizes, int n_in,
                              void* d_out, int out_size) {
    const float* x         = (const float*)d_in[0];
    const int*   edge_row  = (const int*)d_in[1];
    const int*   edge_col  = (const int*)d_in[2];
    const float* edge_vals = (const float*)d_in[3];
    const float* W1        = (const float*)d_in[4];
    const float* b1        = (const float*)d_in[5];
    const float* W2        = (const float*)d_in[6];
    const float* b2        = (const float*)d_in[7];
    float* out = (float*)d_out;

    static cudaStream_t s2 = nullptr;
    static cudaEvent_t evFork = nullptr, evJoin = nullptr;
    if (!s2) {
        cudaStreamCreateWithFlags(&s2, cudaStreamNonBlocking);
        cudaEventCreateWithFlags(&evFork, cudaEventDisableTiming);
        cudaEventCreateWithFlags(&evJoin, cudaEventDisableTiming);
    }

    // fork: GEMM1 (depends only on x, W1) concurrent with CSR build
    cudaEventRecord(evFork, 0);
    cudaStreamWaitEvent(s2, evFork, 0);
    gemm1_kernel<<<M_PAD / 64, 256, 0, s2>>>(x, W1);
    cudaEventRecord(evJoin, s2);

    // CSR build on main stream (R10-exact)
    zero_counts_kernel<<<(N_NODES + 255) / 256, 256>>>();
    hist_kernel<<<(N_EDGES + 255) / 256, 256>>>(edge_row);
    local_scan_kernel<<<NBLK, SCAN_B>>>();
    scan_sums_kernel<<<1, 256>>>();
    add_offsets_kernel<<<NBLK, SCAN_B>>>();
    scatter_kernel<<<(N_EDGES + 255) / 256, 256>>>(edge_row, edge_col, edge_vals);

    // join: spmm1 needs both CSR and support1
    cudaStreamWaitEvent(0, evJoin, 0);
    spmm1_kernel<<<(N_NODES * 32 + 127) / 128, 128>>>(b1);

    gemm2_kernel<<<(N_NODES + 63) / 64, 128>>>(W2);
    spmm2_kernel<<<(N_NODES * 32 + 127) / 128, 128>>>(b2, out);
}